// round 14
// baseline (speedup 1.0000x reference)
#include <cuda_runtime.h>
#include <cstdint>
#include <math.h>

// DecoderLayer fwd: B=4, L=1024, D=1024, H=16, dh=64, Dff=4096, fp32 I/O.
// R13: GEMM inner product switched from tf32 m16n8k8 to bf16 m16n8k16 with
//      3-term error split (AhBh + AhBl + AlBh; residual ~2^-16 << tf32 2^-11).
//      Staging/swizzle/epilogue/modes unchanged; loads use the same
//      conflict-free addresses via a k-permutation (mma k-order invariant).
//      Attention = R12 (pure-tf32 QK, cp.async double-buffer). LN unchanged.

#define BB  4
#define LL  1024
#define DD  1024
#define HH  16
#define DH  64
#define DFF 4096
#define MM  (BB*LL)   // 4096

// Scratch (allocation-free: __device__ globals)
__device__ float g_Q[MM*DD];
__device__ float g_K[MM*DD];
__device__ float g_V[MM*DD];
__device__ float g_ctx[MM*DD];
__device__ float g_X1[MM*DD];
__device__ float g_Hb[(size_t)MM*DFF];
__device__ float g_Y[MM*DD];
__device__ float g_Y2[MM*DD];

static __device__ __forceinline__ float selu_f(float x) {
    const float scale = 1.0507009873554804934193349852946f;
    const float alpha = 1.6732632423543772848170429916717f;
    return x > 0.f ? scale * x : scale * alpha * (__expf(x) - 1.f);
}

static __device__ __forceinline__ uint32_t smem_u32(const void* p) {
    uint32_t a;
    asm("{ .reg .u64 t; cvta.to.shared.u64 t, %1; cvt.u32.u64 %0, t; }"
        : "=r"(a) : "l"(p));
    return a;
}

#define CP16(dst, src) \
    asm volatile("cp.async.cg.shared.global [%0], [%1], 16;" \
                 :: "r"((uint32_t)(dst)), "l"(src) : "memory")
#define CP_COMMIT() asm volatile("cp.async.commit_group;" ::: "memory")
#define CP_WAIT(n)  asm volatile("cp.async.wait_group %0;" :: "n"(n) : "memory")

static __device__ __forceinline__ void mma_tf32(float* c, const uint32_t* a,
                                                const uint32_t* b) {
    asm volatile(
        "mma.sync.aligned.m16n8k8.row.col.f32.tf32.tf32.f32 "
        "{%0,%1,%2,%3}, {%4,%5,%6,%7}, {%8,%9}, {%0,%1,%2,%3};"
        : "+f"(c[0]), "+f"(c[1]), "+f"(c[2]), "+f"(c[3])
        : "r"(a[0]), "r"(a[1]), "r"(a[2]), "r"(a[3]), "r"(b[0]), "r"(b[1]));
}

static __device__ __forceinline__ void mma_bf16(float* c, const uint32_t* a,
                                                const uint32_t* b) {
    asm volatile(
        "mma.sync.aligned.m16n8k16.row.col.f32.bf16.bf16.f32 "
        "{%0,%1,%2,%3}, {%4,%5,%6,%7}, {%8,%9}, {%0,%1,%2,%3};"
        : "+f"(c[0]), "+f"(c[1]), "+f"(c[2]), "+f"(c[3])
        : "r"(a[0]), "r"(a[1]), "r"(a[2]), "r"(a[3]), "r"(b[0]), "r"(b[1]));
}

static __device__ __forceinline__ float tf32r(float x) {
    uint32_t u;
    asm("cvt.rna.tf32.f32 %0, %1;" : "=r"(u) : "f"(x));
    return __uint_as_float(u);
}

// pack {lo16=cvt(lo), hi16=cvt(hi)} (rn) into one .b32
static __device__ __forceinline__ uint32_t pack2(float lo, float hi) {
    uint32_t d;
    asm("cvt.rn.bf16x2.f32 %0, %1, %2;" : "=r"(d) : "f"(hi), "f"(lo));
    return d;
}

// split pair (x0,x1) -> hi-pack + lo-pack (x - float(bf16(x)))
static __device__ __forceinline__ void split2(float x0, float x1,
                                              uint32_t& hi, uint32_t& lo) {
    hi = pack2(x0, x1);
    const float h0 = __uint_as_float(hi << 16);
    const float h1 = __uint_as_float(hi & 0xFFFF0000u);
    lo = pack2(x0 - h0, x1 - h1);
}

// ---------------------------------------------------------------------------
// bf16-split mma.sync GEMM: C[M,N] = A[M,K] @ B[N,K]^T  (torch Linear layout)
// CTA 128x128, BK=32, 128 threads = 4 warps (2Mx2N), warp tile 64x64.
// 3-stage cp.async fp32 tiles (unchanged). Inner loop: per K=16 step, load
// the SAME fp32 words as the old tf32 kernel (k-permutation pi(2t+e)=t+4e
// keeps mma's dot product exact and addresses conflict-free), split to
// bf16 hi/lo in registers, issue 3 bf16 MMAs per (mt,nt).
// MODE 1: C = selu(acc+bias)
// MODE 3: QKV — blockIdx.z selects (B0,C0)/(B1,C1)/(B2,C2), plain store.
// MODE 4: split-K(2) — blockIdx.z selects k-half and C0/C1, plain store.
// ---------------------------------------------------------------------------
#define GK        32
#define TILE_B    16384
#define BUF_BYTES (2 * TILE_B)
#define NSTAGE    3
#define GEMM_SMEM (NSTAGE * BUF_BYTES)  // 98304

template<int MODE>
__global__ __launch_bounds__(128, 2)
void gemm_mma(const float* __restrict__ A,
              const float* __restrict__ B0, const float* __restrict__ B1,
              const float* __restrict__ B2,
              float* __restrict__ C0, float* __restrict__ C1,
              float* __restrict__ C2,
              const float* __restrict__ bias,
              int M, int N, int K)
{
    extern __shared__ char smem[];
    const uint32_t sb = smem_u32(smem);
    const int tid  = threadIdx.x;
    const int wid  = tid >> 5;
    const int lane = tid & 31;
    const int g    = lane >> 2;
    const int tg   = lane & 3;
    const int wm   = wid & 1;
    const int wn   = wid >> 1;
    const int m0   = blockIdx.y * 128;
    const int n0   = blockIdx.x * 128;

    const float* Bw = B0;
    float*       C  = C0;
    if (MODE == 3) {
        if (blockIdx.z == 1)      { Bw = B1; C = C1; }
        else if (blockIdx.z == 2) { Bw = B2; C = C2; }
    }
    int keff = K, koff = 0;
    if (MODE == 4) {
        keff = K >> 1;
        koff = blockIdx.z * keff;
        if (blockIdx.z == 1) C = C1;
    }

    auto stage = [&](int s, int k0) {
        const uint32_t ab = sb + s * BUF_BYTES;
#pragma unroll
        for (int t = 0; t < 8; t++) {
            int idx = tid + t * 128;
            int row = idx >> 3;
            int c   = idx & 7;
            uint32_t off = row * 128 + (((uint32_t)(c ^ (row & 7))) << 4);
            CP16(ab + off,          A  + (size_t)(m0 + row) * K + koff + k0 + c * 4);
            CP16(ab + TILE_B + off, Bw + (size_t)(n0 + row) * K + koff + k0 + c * 4);
        }
        CP_COMMIT();
    };

    const int rowA = wm * 64 + g;
    const int colB = wn * 64 + g;

    float acc[4][8][4];
#pragma unroll
    for (int mt = 0; mt < 4; mt++)
#pragma unroll
        for (int nt = 0; nt < 8; nt++)
#pragma unroll
            for (int r = 0; r < 4; r++) acc[mt][nt][r] = 0.f;

    const int nch = keff / GK;
    stage(0, 0);
    if (nch > 1) stage(1, GK);

    for (int i = 0; i < nch; i++) {
        const int buf = i % NSTAGE;
        if (i + 1 < nch) { CP_WAIT(1); } else { CP_WAIT(0); }
        __syncthreads();
        if (i + 2 < nch) stage((i + 2) % NSTAGE, (i + 2) * GK);

        const float* As = (const float*)(smem + buf * BUF_BYTES);
        const float* Bs = (const float*)(smem + buf * BUF_BYTES + TILE_B);

#pragma unroll
        for (int s = 0; s < 2; s++) {          // two K=16 steps per chunk
            // word offsets for chunks 4s..4s+3 at sub-word tg (conflict-free)
            int off[4];
#pragma unroll
            for (int c = 0; c < 4; c++)
                off[c] = (((4 * s + c) ^ g) << 2) + tg;

            // A fragments: rows g / g+8 per mt; split to bf16 hi/lo
            uint32_t ah[4][4], al[4][4];
#pragma unroll
            for (int mt = 0; mt < 4; mt++) {
                const int r0 = (rowA + mt * 16) * 32;
                const int r8 = r0 + 8 * 32;
                float vg0 = As[r0 + off[0]], vg1 = As[r0 + off[1]];
                float vg2 = As[r0 + off[2]], vg3 = As[r0 + off[3]];
                float v80 = As[r8 + off[0]], v81 = As[r8 + off[1]];
                float v82 = As[r8 + off[2]], v83 = As[r8 + off[3]];
                split2(vg0, vg1, ah[mt][0], al[mt][0]);
                split2(v80, v81, ah[mt][1], al[mt][1]);
                split2(vg2, vg3, ah[mt][2], al[mt][2]);
                split2(v82, v83, ah[mt][3], al[mt][3]);
            }
            // B fragments: n-row g per nt
            uint32_t bh[8][2], bl[8][2];
#pragma unroll
            for (int nt = 0; nt < 8; nt++) {
                const int rr = (colB + nt * 8) * 32;
                float u0 = Bs[rr + off[0]], u1 = Bs[rr + off[1]];
                float u2 = Bs[rr + off[2]], u3 = Bs[rr + off[3]];
                split2(u0, u1, bh[nt][0], bl[nt][0]);
                split2(u2, u3, bh[nt][1], bl[nt][1]);
            }
#pragma unroll
            for (int mt = 0; mt < 4; mt++)
#pragma unroll
                for (int nt = 0; nt < 8; nt++) {
                    mma_bf16(acc[mt][nt], ah[mt], bh[nt]);
                    mma_bf16(acc[mt][nt], ah[mt], bl[nt]);
                    mma_bf16(acc[mt][nt], al[mt], bh[nt]);
                }
        }
    }

#pragma unroll
    for (int mt = 0; mt < 4; mt++) {
        const int r0 = m0 + wm * 64 + mt * 16 + g;
#pragma unroll
        for (int nt = 0; nt < 8; nt++) {
            const int col = n0 + wn * 64 + nt * 8 + tg * 2;
            float v0 = acc[mt][nt][0], v1 = acc[mt][nt][1];
            float v2 = acc[mt][nt][2], v3 = acc[mt][nt][3];
            if (MODE == 1) {
                v0 = selu_f(v0 + bias[col]);     v1 = selu_f(v1 + bias[col + 1]);
                v2 = selu_f(v2 + bias[col]);     v3 = selu_f(v3 + bias[col + 1]);
            }
            *(float2*)&C[(size_t)r0 * N + col]       = make_float2(v0, v1);
            *(float2*)&C[(size_t)(r0 + 8) * N + col] = make_float2(v2, v3);
        }
    }
}

// ---------------------------------------------------------------------------
// Tensor-core flash attention (R12, unchanged). grid=(16, B*H), block=128.
// ---------------------------------------------------------------------------
#define SQK 68
#define SV  72
#define STG_F (64*SQK + 64*SV)                   // floats per K/V stage
#define ATT_SMEM ((64*SQK + 2*STG_F) * 4)        // 91136 B

__global__ __launch_bounds__(128)
void attn_tc(const float* __restrict__ Q, const float* __restrict__ K,
             const float* __restrict__ V, float* __restrict__ O)
{
    extern __shared__ float sm[];
    float* Qh = sm;
    float* St = Qh + 64*SQK;          // stage s: Kr=St+s*STG_F, Vs=Kr+64*SQK

    const int qb = (int)gridDim.x - 1 - (int)blockIdx.x;  // heavy blocks first
    const int q0 = qb * 64;
    const int bh = blockIdx.y;
    const int b  = bh >> 4;
    const int h  = bh & 15;
    const size_t base = (size_t)b * LL * DD + (size_t)h * DH;

    const int tid  = threadIdx.x;
    const int lane = tid & 31;
    const int g    = lane >> 2;
    const int tg   = lane & 3;
    const int qw   = (tid >> 5) * 16;

    const uint32_t stb = smem_u32(St);

    auto prefetch = [&](int s, int k0) {
        const uint32_t kb = stb + (uint32_t)(s * STG_F) * 4u;
        const uint32_t vb = kb + 64u * SQK * 4u;
#pragma unroll
        for (int i = 0; i < 8; i++) {
            int idx = tid + i * 128;
            int r = idx >> 4, c4 = (idx & 15) * 4;
            CP16(kb + (uint32_t)(r * SQK + c4) * 4u,
                 K + base + (size_t)(k0 + r) * DD + c4);
            CP16(vb + (uint32_t)(r * SV + c4) * 4u,
                 V + base + (size_t)(k0 + r) * DD + c4);
        }
        CP_COMMIT();
    };

    prefetch(0, 0);

    // Load Q tile: scale by 1/8, round to tf32 once.
#pragma unroll
    for (int i = 0; i < 8; i++) {
        int idx = tid + i * 128;
        int r = idx >> 4, c4 = (idx & 15) * 4;
        float4 v = *(const float4*)&Q[base + (size_t)(q0 + r) * DD + c4];
        float4 hi;
        hi.x = tf32r(v.x * 0.125f);
        hi.y = tf32r(v.y * 0.125f);
        hi.z = tf32r(v.z * 0.125f);
        hi.w = tf32r(v.w * 0.125f);
        *(float4*)&Qh[r * SQK + c4] = hi;
    }

    float m0r = -1e30f, m1r = -1e30f, l0r = 0.f, l1r = 0.f;
    float oacc[8][4];
#pragma unroll
    for (int nb = 0; nb < 8; nb++)
#pragma unroll
        for (int r = 0; r < 4; r++) oacc[nb][r] = 0.f;

    const int ntile = qb + 1;
    for (int kt = 0; kt < ntile; kt++) {
        const int k0 = kt * 64;
        if (kt + 1 < ntile) {
            prefetch((kt + 1) & 1, (kt + 1) * 64);
            CP_WAIT(1);
        } else {
            CP_WAIT(0);
        }
        __syncthreads();

        const float* Kr = St + (kt & 1) * STG_F;
        const float* Vs = Kr + 64 * SQK;

        float sacc[8][4];
#pragma unroll
        for (int nb = 0; nb < 8; nb++)
#pragma unroll
            for (int r = 0; r < 4; r++) sacc[nb][r] = 0.f;

#pragma unroll
        for (int ks = 0; ks < 8; ks++) {
            const int d0 = ks * 8 + tg;
            uint32_t ah[4];
            ah[0] = __float_as_uint(Qh[(qw + g    ) * SQK + d0    ]);
            ah[1] = __float_as_uint(Qh[(qw + g + 8) * SQK + d0    ]);
            ah[2] = __float_as_uint(Qh[(qw + g    ) * SQK + d0 + 4]);
            ah[3] = __float_as_uint(Qh[(qw + g + 8) * SQK + d0 + 4]);
#pragma unroll
            for (int nb = 0; nb < 8; nb++) {
                uint32_t bh2[2];
                bh2[0] = __float_as_uint(tf32r(Kr[(nb * 8 + g) * SQK + d0    ]));
                bh2[1] = __float_as_uint(tf32r(Kr[(nb * 8 + g) * SQK + d0 + 4]));
                mma_tf32(sacc[nb], ah, bh2);
            }
        }

        if (k0 == q0) {
#pragma unroll
            for (int nb = 0; nb < 8; nb++) {
                const int col = nb * 8 + 2 * tg;
                const int r0 = qw + g, r1 = r0 + 8;
                if (col     > r0) sacc[nb][0] = -1e30f;
                if (col + 1 > r0) sacc[nb][1] = -1e30f;
                if (col     > r1) sacc[nb][2] = -1e30f;
                if (col + 1 > r1) sacc[nb][3] = -1e30f;
            }
        }

        float mx0 = -1e30f, mx1 = -1e30f;
#pragma unroll
        for (int nb = 0; nb < 8; nb++) {
            mx0 = fmaxf(mx0, fmaxf(sacc[nb][0], sacc[nb][1]));
            mx1 = fmaxf(mx1, fmaxf(sacc[nb][2], sacc[nb][3]));
        }
        mx0 = fmaxf(mx0, __shfl_xor_sync(0xffffffffu, mx0, 1));
        mx0 = fmaxf(mx0, __shfl_xor_sync(0xffffffffu, mx0, 2));
        mx1 = fmaxf(mx1, __shfl_xor_sync(0xffffffffu, mx1, 1));
        mx1 = fmaxf(mx1, __shfl_xor_sync(0xffffffffu, mx1, 2));

        const float nm0 = fmaxf(m0r, mx0), nm1 = fmaxf(m1r, mx1);
        const float al0 = __expf(m0r - nm0), al1 = __expf(m1r - nm1);
        float rs0 = 0.f, rs1 = 0.f;
#pragma unroll
        for (int nb = 0; nb < 8; nb++) {
            sacc[nb][0] = __expf(sacc[nb][0] - nm0);
            sacc[nb][1] = __expf(sacc[nb][1] - nm0);
            sacc[nb][2] = __expf(sacc[nb][2] - nm1);
            sacc[nb][3] = __expf(sacc[nb][3] - nm1);
            rs0 += sacc[nb][0] + sacc[nb][1];
            rs1 += sacc[nb][2] + sacc[nb][3];
        }
        rs0 += __shfl_xor_sync(0xffffffffu, rs0, 1);
        rs0 += __shfl_xor_sync(0xffffffffu, rs0, 2);
        rs1 += __shfl_xor_sync(0xffffffffu, rs1, 1);
        rs1 += __shfl_xor_sync(0xffffffffu, rs1, 2);
        l0r = l0r * al0 + rs0;
        l1r = l1r * al1 + rs1;
        m0r = nm0; m1r = nm1;
#pragma unroll
        for (int nb = 0; nb < 8; nb++) {
            oacc[nb][0] *= al0; oacc[nb][1] *= al0;
            oacc[nb][2] *= al1; oacc[nb][3] *= al1;
        }

#pragma unroll
        for (int ks2 = 0; ks2 < 8; ks2++) {
            const int sA = (lane & 28) | (tg >> 1);
            const int sB = sA + 2;
            const float q0v = __shfl_sync(0xffffffffu, sacc[ks2][0], sA);
            const float q1v = __shfl_sync(0xffffffffu, sacc[ks2][1], sA);
            const float q2v = __shfl_sync(0xffffffffu, sacc[ks2][2], sA);
            const float q3v = __shfl_sync(0xffffffffu, sacc[ks2][3], sA);
            const float r0v = __shfl_sync(0xffffffffu, sacc[ks2][0], sB);
            const float r1v = __shfl_sync(0xffffffffu, sacc[ks2][1], sB);
            const float r2v = __shfl_sync(0xffffffffu, sacc[ks2][2], sB);
            const float r3v = __shfl_sync(0xffffffffu, sacc[ks2][3], sB);
            const bool oddc = (tg & 1);
            uint32_t aP[4];
            aP[0] = __float_as_uint(oddc ? q1v : q0v);
            aP[1] = __float_as_uint(oddc ? q3v : q2v);
            aP[2] = __float_as_uint(oddc ? r1v : r0v);
            aP[3] = __float_as_uint(oddc ? r3v : r2v);
#pragma unroll
            for (int nb2 = 0; nb2 < 8; nb2++) {
                uint32_t bV[2];
                bV[0] = __float_as_uint(Vs[(ks2 * 8 + tg    ) * SV + nb2 * 8 + g]);
                bV[1] = __float_as_uint(Vs[(ks2 * 8 + tg + 4) * SV + nb2 * 8 + g]);
                mma_tf32(oacc[nb2], aP, bV);
            }
        }
        __syncthreads();
    }

    const float inv0 = 1.f / l0r, inv1 = 1.f / l1r;
    const int r0 = q0 + qw + g, r1 = r0 + 8;
#pragma unroll
    for (int nb = 0; nb < 8; nb++) {
        const int c = nb * 8 + tg * 2;
        *(float2*)&O[base + (size_t)r0 * DD + c] =
            make_float2(oacc[nb][0] * inv0, oacc[nb][1] * inv0);
        *(float2*)&O[base + (size_t)r1 * DD + c] =
            make_float2(oacc[nb][2] * inv1, oacc[nb][3] * inv1);
    }
}

// ---------------------------------------------------------------------------
// LayerNorm over last dim (1024). Input = x [+ add] [+ add2] [+ brow[col]].
// ---------------------------------------------------------------------------
__global__ __launch_bounds__(256)
void ln_kernel(const float* __restrict__ x, const float* __restrict__ add,
               const float* __restrict__ add2, const float* __restrict__ brow,
               const float* __restrict__ g, const float* __restrict__ bta,
               float* __restrict__ out)
{
    const int row = blockIdx.x;
    const int tid = threadIdx.x;
    const size_t off = (size_t)row * DD + tid * 4;

    float4 v = *(const float4*)&x[off];
    if (add != nullptr) {
        float4 a = *(const float4*)&add[off];
        v.x += a.x; v.y += a.y; v.z += a.z; v.w += a.w;
    }
    if (add2 != nullptr) {
        float4 a = *(const float4*)&add2[off];
        v.x += a.x; v.y += a.y; v.z += a.z; v.w += a.w;
    }
    if (brow != nullptr) {
        float4 a = *(const float4*)&brow[tid * 4];
        v.x += a.x; v.y += a.y; v.z += a.z; v.w += a.w;
    }
    float s1 = v.x + v.y + v.z + v.w;
    float s2 = v.x*v.x + v.y*v.y + v.z*v.z + v.w*v.w;
#pragma unroll
    for (int o2 = 16; o2; o2 >>= 1) {
        s1 += __shfl_xor_sync(0xffffffffu, s1, o2);
        s2 += __shfl_xor_sync(0xffffffffu, s2, o2);
    }
    __shared__ float r1[8], r2[8], mb[2];
    const int lane = tid & 31, wd = tid >> 5;
    if (lane == 0) { r1[wd] = s1; r2[wd] = s2; }
    __syncthreads();
    if (tid == 0) {
        float a = 0.f, c = 0.f;
#pragma unroll
        for (int w = 0; w < 8; w++) { a += r1[w]; c += r2[w]; }
        const float mean = a * (1.f / DD);
        const float var  = c * (1.f / DD) - mean * mean;
        mb[0] = mean;
        mb[1] = rsqrtf(var + 1e-5f);
    }
    __syncthreads();
    const float mean = mb[0], rstd = mb[1];

    float4 gg = *(const float4*)&g[tid * 4];
    float4 bb = *(const float4*)&bta[tid * 4];
    float4 r;
    r.x = (v.x - mean) * rstd * gg.x + bb.x;
    r.y = (v.y - mean) * rstd * gg.y + bb.y;
    r.z = (v.z - mean) * rstd * gg.z + bb.z;
    r.w = (v.w - mean) * rstd * gg.w + bb.w;
    *(float4*)&out[off] = r;
}

// ---------------------------------------------------------------------------
extern "C" void kernel_launch(void* const* d_in, const int* in_sizes, int n_in,
                              void* d_out, int out_size)
{
    const float* X     = (const float*)d_in[0];
    const float* wq    = (const float*)d_in[1];
    const float* wk    = (const float*)d_in[2];
    const float* wv    = (const float*)d_in[3];
    const float* ln1_g = (const float*)d_in[4];
    const float* ln1_b = (const float*)d_in[5];
    const float* w1    = (const float*)d_in[6];
    const float* b1    = (const float*)d_in[7];
    const float* w2    = (const float*)d_in[8];
    const float* b2    = (const float*)d_in[9];
    const float* ln2_g = (const float*)d_in[10];
    const float* ln2_b = (const float*)d_in[11];
    float* out = (float*)d_out;

    float *pQ, *pK, *pV, *pCtx, *pX1, *pHb, *pY, *pY2;
    cudaGetSymbolAddress((void**)&pQ,   g_Q);
    cudaGetSymbolAddress((void**)&pK,   g_K);
    cudaGetSymbolAddress((void**)&pV,   g_V);
    cudaGetSymbolAddress((void**)&pCtx, g_ctx);
    cudaGetSymbolAddress((void**)&pX1,  g_X1);
    cudaGetSymbolAddress((void**)&pHb,  g_Hb);
    cudaGetSymbolAddress((void**)&pY,   g_Y);
    cudaGetSymbolAddress((void**)&pY2,  g_Y2);

    cudaFuncSetAttribute(gemm_mma<1>, cudaFuncAttributeMaxDynamicSharedMemorySize, GEMM_SMEM);
    cudaFuncSetAttribute(gemm_mma<3>, cudaFuncAttributeMaxDynamicSharedMemorySize, GEMM_SMEM);
    cudaFuncSetAttribute(gemm_mma<4>, cudaFuncAttributeMaxDynamicSharedMemorySize, GEMM_SMEM);
    cudaFuncSetAttribute(attn_tc,     cudaFuncAttributeMaxDynamicSharedMemorySize, ATT_SMEM);

    const dim3 blk(128);
    // Fused QKV projection (blockIdx.z selects weight/output)
    gemm_mma<3><<<dim3(DD/128, MM/128, 3), blk, GEMM_SMEM>>>(
        X, wq, wk, wv, pQ, pK, pV, nullptr, MM, DD, DD);
    attn_tc<<<dim3(LL/64, BB*HH), 128, ATT_SMEM>>>(pQ, pK, pV, pCtx);
    ln_kernel<<<MM, 256>>>(X, pCtx, nullptr, nullptr, ln1_g, ln1_b, pX1);
    // FFN up + SELU
    gemm_mma<1><<<dim3(DFF/128, MM/128), blk, GEMM_SMEM>>>(
        pX1, w1, nullptr, nullptr, pHb, nullptr, nullptr, b1, MM, DFF, DD);
    // FFN down, split-K=2
    gemm_mma<4><<<dim3(DD/128, MM/128, 2), blk, GEMM_SMEM>>>(
        pHb, w2, nullptr, nullptr, pY, pY2, nullptr, nullptr, MM, DD, DFF);
    // LN2( Y + Y2 + X1 + b2 ) -> out
    ln_kernel<<<MM, 256>>>(pY, pY2, pX1, b2, ln2_g, ln2_b, out);
}

// round 15
// speedup vs baseline: 1.9197x; 1.9197x over previous
#include <cuda_runtime.h>
#include <cstdint>
#include <math.h>

// DecoderLayer fwd: B=4, L=1024, D=1024, H=16, dh=64, Dff=4096, fp32 I/O.
// R14: GEMMs on PURE fp16 m16n8k16 (no split). fp16 operand rounding eps
//      (2^-11) == tf32, so accuracy ~= the long-measured 7.2e-4; MMA count
//      halves and R13 proved k16 runs at the same per-instruction rate as
//      k8-tf32 (=> 2x per-MAC). k-permutation keeps the tf32 kernel's
//      conflict-free smem addresses. Attention = R12. LN unchanged.

#define BB  4
#define LL  1024
#define DD  1024
#define HH  16
#define DH  64
#define DFF 4096
#define MM  (BB*LL)   // 4096

// Scratch (allocation-free: __device__ globals)
__device__ float g_Q[MM*DD];
__device__ float g_K[MM*DD];
__device__ float g_V[MM*DD];
__device__ float g_ctx[MM*DD];
__device__ float g_X1[MM*DD];
__device__ float g_Hb[(size_t)MM*DFF];
__device__ float g_Y[MM*DD];
__device__ float g_Y2[MM*DD];

static __device__ __forceinline__ float selu_f(float x) {
    const float scale = 1.0507009873554804934193349852946f;
    const float alpha = 1.6732632423543772848170429916717f;
    return x > 0.f ? scale * x : scale * alpha * (__expf(x) - 1.f);
}

static __device__ __forceinline__ uint32_t smem_u32(const void* p) {
    uint32_t a;
    asm("{ .reg .u64 t; cvta.to.shared.u64 t, %1; cvt.u32.u64 %0, t; }"
        : "=r"(a) : "l"(p));
    return a;
}

#define CP16(dst, src) \
    asm volatile("cp.async.cg.shared.global [%0], [%1], 16;" \
                 :: "r"((uint32_t)(dst)), "l"(src) : "memory")
#define CP_COMMIT() asm volatile("cp.async.commit_group;" ::: "memory")
#define CP_WAIT(n)  asm volatile("cp.async.wait_group %0;" :: "n"(n) : "memory")

static __device__ __forceinline__ void mma_tf32(float* c, const uint32_t* a,
                                                const uint32_t* b) {
    asm volatile(
        "mma.sync.aligned.m16n8k8.row.col.f32.tf32.tf32.f32 "
        "{%0,%1,%2,%3}, {%4,%5,%6,%7}, {%8,%9}, {%0,%1,%2,%3};"
        : "+f"(c[0]), "+f"(c[1]), "+f"(c[2]), "+f"(c[3])
        : "r"(a[0]), "r"(a[1]), "r"(a[2]), "r"(a[3]), "r"(b[0]), "r"(b[1]));
}

static __device__ __forceinline__ void mma_f16(float* c, const uint32_t* a,
                                               const uint32_t* b) {
    asm volatile(
        "mma.sync.aligned.m16n8k16.row.col.f32.f16.f16.f32 "
        "{%0,%1,%2,%3}, {%4,%5,%6,%7}, {%8,%9}, {%0,%1,%2,%3};"
        : "+f"(c[0]), "+f"(c[1]), "+f"(c[2]), "+f"(c[3])
        : "r"(a[0]), "r"(a[1]), "r"(a[2]), "r"(a[3]), "r"(b[0]), "r"(b[1]));
}

static __device__ __forceinline__ float tf32r(float x) {
    uint32_t u;
    asm("cvt.rna.tf32.f32 %0, %1;" : "=r"(u) : "f"(x));
    return __uint_as_float(u);
}

// pack two fp32 into one fp16x2: low half = lo, high half = hi
static __device__ __forceinline__ uint32_t packh(float lo, float hi) {
    uint32_t d;
    asm("cvt.rn.f16x2.f32 %0, %1, %2;" : "=r"(d) : "f"(hi), "f"(lo));
    return d;
}

// ---------------------------------------------------------------------------
// fp16 mma.sync GEMM: C[M,N] = A[M,K] @ B[N,K]^T  (torch Linear layout)
// CTA 128x128, BK=32, 128 threads = 4 warps (2Mx2N), warp tile 64x64.
// 3-stage cp.async fp32 tiles (unchanged). Inner loop: per K=16 step, read
// the tf32 kernel's conflict-free words (k-permutation: register slot
// (tg,e) <-> chunk-word off[2e]/off[2e+1]; identical for A and B so the
// mma dot product is exact), cvt.rn.f16x2 in registers, 1 MMA per (mt,nt).
// MODE 1: C = selu(acc+bias)
// MODE 3: QKV — blockIdx.z selects (B0,C0)/(B1,C1)/(B2,C2), plain store.
// MODE 4: split-K(2) — blockIdx.z selects k-half and C0/C1, plain store.
// ---------------------------------------------------------------------------
#define GK        32
#define TILE_B    16384
#define BUF_BYTES (2 * TILE_B)
#define NSTAGE    3
#define GEMM_SMEM (NSTAGE * BUF_BYTES)  // 98304

template<int MODE>
__global__ __launch_bounds__(128, 2)
void gemm_mma(const float* __restrict__ A,
              const float* __restrict__ B0, const float* __restrict__ B1,
              const float* __restrict__ B2,
              float* __restrict__ C0, float* __restrict__ C1,
              float* __restrict__ C2,
              const float* __restrict__ bias,
              int M, int N, int K)
{
    extern __shared__ char smem[];
    const uint32_t sb = smem_u32(smem);
    const int tid  = threadIdx.x;
    const int wid  = tid >> 5;
    const int lane = tid & 31;
    const int g    = lane >> 2;
    const int tg   = lane & 3;
    const int wm   = wid & 1;
    const int wn   = wid >> 1;
    const int m0   = blockIdx.y * 128;
    const int n0   = blockIdx.x * 128;

    const float* Bw = B0;
    float*       C  = C0;
    if (MODE == 3) {
        if (blockIdx.z == 1)      { Bw = B1; C = C1; }
        else if (blockIdx.z == 2) { Bw = B2; C = C2; }
    }
    int keff = K, koff = 0;
    if (MODE == 4) {
        keff = K >> 1;
        koff = blockIdx.z * keff;
        if (blockIdx.z == 1) C = C1;
    }

    auto stage = [&](int s, int k0) {
        const uint32_t ab = sb + s * BUF_BYTES;
#pragma unroll
        for (int t = 0; t < 8; t++) {
            int idx = tid + t * 128;
            int row = idx >> 3;
            int c   = idx & 7;
            uint32_t off = row * 128 + (((uint32_t)(c ^ (row & 7))) << 4);
            CP16(ab + off,          A  + (size_t)(m0 + row) * K + koff + k0 + c * 4);
            CP16(ab + TILE_B + off, Bw + (size_t)(n0 + row) * K + koff + k0 + c * 4);
        }
        CP_COMMIT();
    };

    const int rowA = wm * 64 + g;
    const int colB = wn * 64 + g;

    float acc[4][8][4];
#pragma unroll
    for (int mt = 0; mt < 4; mt++)
#pragma unroll
        for (int nt = 0; nt < 8; nt++)
#pragma unroll
            for (int r = 0; r < 4; r++) acc[mt][nt][r] = 0.f;

    const int nch = keff / GK;
    stage(0, 0);
    if (nch > 1) stage(1, GK);

    for (int i = 0; i < nch; i++) {
        const int buf = i % NSTAGE;
        if (i + 1 < nch) { CP_WAIT(1); } else { CP_WAIT(0); }
        __syncthreads();
        if (i + 2 < nch) stage((i + 2) % NSTAGE, (i + 2) * GK);

        const float* As = (const float*)(smem + buf * BUF_BYTES);
        const float* Bs = (const float*)(smem + buf * BUF_BYTES + TILE_B);

#pragma unroll
        for (int s = 0; s < 2; s++) {          // two K=16 steps per chunk
            int off[4];
#pragma unroll
            for (int c = 0; c < 4; c++)
                off[c] = (((4 * s + c) ^ g) << 2) + tg;

            // A fragments: rows g / g+8 per mt; pack fp32 pairs -> fp16x2
            uint32_t a[4][4];
#pragma unroll
            for (int mt = 0; mt < 4; mt++) {
                const int r0 = (rowA + mt * 16) * 32;
                const int r8 = r0 + 8 * 32;
                a[mt][0] = packh(As[r0 + off[0]], As[r0 + off[1]]);
                a[mt][1] = packh(As[r8 + off[0]], As[r8 + off[1]]);
                a[mt][2] = packh(As[r0 + off[2]], As[r0 + off[3]]);
                a[mt][3] = packh(As[r8 + off[2]], As[r8 + off[3]]);
            }
            // B fragments: n-row g per nt
            uint32_t b[8][2];
#pragma unroll
            for (int nt = 0; nt < 8; nt++) {
                const int rr = (colB + nt * 8) * 32;
                b[nt][0] = packh(Bs[rr + off[0]], Bs[rr + off[1]]);
                b[nt][1] = packh(Bs[rr + off[2]], Bs[rr + off[3]]);
            }
#pragma unroll
            for (int mt = 0; mt < 4; mt++)
#pragma unroll
                for (int nt = 0; nt < 8; nt++)
                    mma_f16(acc[mt][nt], a[mt], b[nt]);
        }
    }

#pragma unroll
    for (int mt = 0; mt < 4; mt++) {
        const int r0 = m0 + wm * 64 + mt * 16 + g;
#pragma unroll
        for (int nt = 0; nt < 8; nt++) {
            const int col = n0 + wn * 64 + nt * 8 + tg * 2;
            float v0 = acc[mt][nt][0], v1 = acc[mt][nt][1];
            float v2 = acc[mt][nt][2], v3 = acc[mt][nt][3];
            if (MODE == 1) {
                v0 = selu_f(v0 + bias[col]);     v1 = selu_f(v1 + bias[col + 1]);
                v2 = selu_f(v2 + bias[col]);     v3 = selu_f(v3 + bias[col + 1]);
            }
            *(float2*)&C[(size_t)r0 * N + col]       = make_float2(v0, v1);
            *(float2*)&C[(size_t)(r0 + 8) * N + col] = make_float2(v2, v3);
        }
    }
}

// ---------------------------------------------------------------------------
// Tensor-core flash attention (R12, unchanged). grid=(16, B*H), block=128.
// ---------------------------------------------------------------------------
#define SQK 68
#define SV  72
#define STG_F (64*SQK + 64*SV)                   // floats per K/V stage
#define ATT_SMEM ((64*SQK + 2*STG_F) * 4)        // 91136 B

__global__ __launch_bounds__(128)
void attn_tc(const float* __restrict__ Q, const float* __restrict__ K,
             const float* __restrict__ V, float* __restrict__ O)
{
    extern __shared__ float sm[];
    float* Qh = sm;
    float* St = Qh + 64*SQK;          // stage s: Kr=St+s*STG_F, Vs=Kr+64*SQK

    const int qb = (int)gridDim.x - 1 - (int)blockIdx.x;  // heavy blocks first
    const int q0 = qb * 64;
    const int bh = blockIdx.y;
    const int b  = bh >> 4;
    const int h  = bh & 15;
    const size_t base = (size_t)b * LL * DD + (size_t)h * DH;

    const int tid  = threadIdx.x;
    const int lane = tid & 31;
    const int g    = lane >> 2;
    const int tg   = lane & 3;
    const int qw   = (tid >> 5) * 16;

    const uint32_t stb = smem_u32(St);

    auto prefetch = [&](int s, int k0) {
        const uint32_t kb = stb + (uint32_t)(s * STG_F) * 4u;
        const uint32_t vb = kb + 64u * SQK * 4u;
#pragma unroll
        for (int i = 0; i < 8; i++) {
            int idx = tid + i * 128;
            int r = idx >> 4, c4 = (idx & 15) * 4;
            CP16(kb + (uint32_t)(r * SQK + c4) * 4u,
                 K + base + (size_t)(k0 + r) * DD + c4);
            CP16(vb + (uint32_t)(r * SV + c4) * 4u,
                 V + base + (size_t)(k0 + r) * DD + c4);
        }
        CP_COMMIT();
    };

    prefetch(0, 0);

    // Load Q tile: scale by 1/8, round to tf32 once.
#pragma unroll
    for (int i = 0; i < 8; i++) {
        int idx = tid + i * 128;
        int r = idx >> 4, c4 = (idx & 15) * 4;
        float4 v = *(const float4*)&Q[base + (size_t)(q0 + r) * DD + c4];
        float4 hi;
        hi.x = tf32r(v.x * 0.125f);
        hi.y = tf32r(v.y * 0.125f);
        hi.z = tf32r(v.z * 0.125f);
        hi.w = tf32r(v.w * 0.125f);
        *(float4*)&Qh[r * SQK + c4] = hi;
    }

    float m0r = -1e30f, m1r = -1e30f, l0r = 0.f, l1r = 0.f;
    float oacc[8][4];
#pragma unroll
    for (int nb = 0; nb < 8; nb++)
#pragma unroll
        for (int r = 0; r < 4; r++) oacc[nb][r] = 0.f;

    const int ntile = qb + 1;
    for (int kt = 0; kt < ntile; kt++) {
        const int k0 = kt * 64;
        if (kt + 1 < ntile) {
            prefetch((kt + 1) & 1, (kt + 1) * 64);
            CP_WAIT(1);
        } else {
            CP_WAIT(0);
        }
        __syncthreads();

        const float* Kr = St + (kt & 1) * STG_F;
        const float* Vs = Kr + 64 * SQK;

        float sacc[8][4];
#pragma unroll
        for (int nb = 0; nb < 8; nb++)
#pragma unroll
            for (int r = 0; r < 4; r++) sacc[nb][r] = 0.f;

#pragma unroll
        for (int ks = 0; ks < 8; ks++) {
            const int d0 = ks * 8 + tg;
            uint32_t ah[4];
            ah[0] = __float_as_uint(Qh[(qw + g    ) * SQK + d0    ]);
            ah[1] = __float_as_uint(Qh[(qw + g + 8) * SQK + d0    ]);
            ah[2] = __float_as_uint(Qh[(qw + g    ) * SQK + d0 + 4]);
            ah[3] = __float_as_uint(Qh[(qw + g + 8) * SQK + d0 + 4]);
#pragma unroll
            for (int nb = 0; nb < 8; nb++) {
                uint32_t bh2[2];
                bh2[0] = __float_as_uint(tf32r(Kr[(nb * 8 + g) * SQK + d0    ]));
                bh2[1] = __float_as_uint(tf32r(Kr[(nb * 8 + g) * SQK + d0 + 4]));
                mma_tf32(sacc[nb], ah, bh2);
            }
        }

        if (k0 == q0) {
#pragma unroll
            for (int nb = 0; nb < 8; nb++) {
                const int col = nb * 8 + 2 * tg;
                const int r0 = qw + g, r1 = r0 + 8;
                if (col     > r0) sacc[nb][0] = -1e30f;
                if (col + 1 > r0) sacc[nb][1] = -1e30f;
                if (col     > r1) sacc[nb][2] = -1e30f;
                if (col + 1 > r1) sacc[nb][3] = -1e30f;
            }
        }

        float mx0 = -1e30f, mx1 = -1e30f;
#pragma unroll
        for (int nb = 0; nb < 8; nb++) {
            mx0 = fmaxf(mx0, fmaxf(sacc[nb][0], sacc[nb][1]));
            mx1 = fmaxf(mx1, fmaxf(sacc[nb][2], sacc[nb][3]));
        }
        mx0 = fmaxf(mx0, __shfl_xor_sync(0xffffffffu, mx0, 1));
        mx0 = fmaxf(mx0, __shfl_xor_sync(0xffffffffu, mx0, 2));
        mx1 = fmaxf(mx1, __shfl_xor_sync(0xffffffffu, mx1, 1));
        mx1 = fmaxf(mx1, __shfl_xor_sync(0xffffffffu, mx1, 2));

        const float nm0 = fmaxf(m0r, mx0), nm1 = fmaxf(m1r, mx1);
        const float al0 = __expf(m0r - nm0), al1 = __expf(m1r - nm1);
        float rs0 = 0.f, rs1 = 0.f;
#pragma unroll
        for (int nb = 0; nb < 8; nb++) {
            sacc[nb][0] = __expf(sacc[nb][0] - nm0);
            sacc[nb][1] = __expf(sacc[nb][1] - nm0);
            sacc[nb][2] = __expf(sacc[nb][2] - nm1);
            sacc[nb][3] = __expf(sacc[nb][3] - nm1);
            rs0 += sacc[nb][0] + sacc[nb][1];
            rs1 += sacc[nb][2] + sacc[nb][3];
        }
        rs0 += __shfl_xor_sync(0xffffffffu, rs0, 1);
        rs0 += __shfl_xor_sync(0xffffffffu, rs0, 2);
        rs1 += __shfl_xor_sync(0xffffffffu, rs1, 1);
        rs1 += __shfl_xor_sync(0xffffffffu, rs1, 2);
        l0r = l0r * al0 + rs0;
        l1r = l1r * al1 + rs1;
        m0r = nm0; m1r = nm1;
#pragma unroll
        for (int nb = 0; nb < 8; nb++) {
            oacc[nb][0] *= al0; oacc[nb][1] *= al0;
            oacc[nb][2] *= al1; oacc[nb][3] *= al1;
        }

#pragma unroll
        for (int ks2 = 0; ks2 < 8; ks2++) {
            const int sA = (lane & 28) | (tg >> 1);
            const int sB = sA + 2;
            const float q0v = __shfl_sync(0xffffffffu, sacc[ks2][0], sA);
            const float q1v = __shfl_sync(0xffffffffu, sacc[ks2][1], sA);
            const float q2v = __shfl_sync(0xffffffffu, sacc[ks2][2], sA);
            const float q3v = __shfl_sync(0xffffffffu, sacc[ks2][3], sA);
            const float r0v = __shfl_sync(0xffffffffu, sacc[ks2][0], sB);
            const float r1v = __shfl_sync(0xffffffffu, sacc[ks2][1], sB);
            const float r2v = __shfl_sync(0xffffffffu, sacc[ks2][2], sB);
            const float r3v = __shfl_sync(0xffffffffu, sacc[ks2][3], sB);
            const bool oddc = (tg & 1);
            uint32_t aP[4];
            aP[0] = __float_as_uint(oddc ? q1v : q0v);
            aP[1] = __float_as_uint(oddc ? q3v : q2v);
            aP[2] = __float_as_uint(oddc ? r1v : r0v);
            aP[3] = __float_as_uint(oddc ? r3v : r2v);
#pragma unroll
            for (int nb2 = 0; nb2 < 8; nb2++) {
                uint32_t bV[2];
                bV[0] = __float_as_uint(Vs[(ks2 * 8 + tg    ) * SV + nb2 * 8 + g]);
                bV[1] = __float_as_uint(Vs[(ks2 * 8 + tg + 4) * SV + nb2 * 8 + g]);
                mma_tf32(oacc[nb2], aP, bV);
            }
        }
        __syncthreads();
    }

    const float inv0 = 1.f / l0r, inv1 = 1.f / l1r;
    const int r0 = q0 + qw + g, r1 = r0 + 8;
#pragma unroll
    for (int nb = 0; nb < 8; nb++) {
        const int c = nb * 8 + tg * 2;
        *(float2*)&O[base + (size_t)r0 * DD + c] =
            make_float2(oacc[nb][0] * inv0, oacc[nb][1] * inv0);
        *(float2*)&O[base + (size_t)r1 * DD + c] =
            make_float2(oacc[nb][2] * inv1, oacc[nb][3] * inv1);
    }
}

// ---------------------------------------------------------------------------
// LayerNorm over last dim (1024). Input = x [+ add] [+ add2] [+ brow[col]].
// ---------------------------------------------------------------------------
__global__ __launch_bounds__(256)
void ln_kernel(const float* __restrict__ x, const float* __restrict__ add,
               const float* __restrict__ add2, const float* __restrict__ brow,
               const float* __restrict__ g, const float* __restrict__ bta,
               float* __restrict__ out)
{
    const int row = blockIdx.x;
    const int tid = threadIdx.x;
    const size_t off = (size_t)row * DD + tid * 4;

    float4 v = *(const float4*)&x[off];
    if (add != nullptr) {
        float4 a = *(const float4*)&add[off];
        v.x += a.x; v.y += a.y; v.z += a.z; v.w += a.w;
    }
    if (add2 != nullptr) {
        float4 a = *(const float4*)&add2[off];
        v.x += a.x; v.y += a.y; v.z += a.z; v.w += a.w;
    }
    if (brow != nullptr) {
        float4 a = *(const float4*)&brow[tid * 4];
        v.x += a.x; v.y += a.y; v.z += a.z; v.w += a.w;
    }
    float s1 = v.x + v.y + v.z + v.w;
    float s2 = v.x*v.x + v.y*v.y + v.z*v.z + v.w*v.w;
#pragma unroll
    for (int o2 = 16; o2; o2 >>= 1) {
        s1 += __shfl_xor_sync(0xffffffffu, s1, o2);
        s2 += __shfl_xor_sync(0xffffffffu, s2, o2);
    }
    __shared__ float r1[8], r2[8], mb[2];
    const int lane = tid & 31, wd = tid >> 5;
    if (lane == 0) { r1[wd] = s1; r2[wd] = s2; }
    __syncthreads();
    if (tid == 0) {
        float a = 0.f, c = 0.f;
#pragma unroll
        for (int w = 0; w < 8; w++) { a += r1[w]; c += r2[w]; }
        const float mean = a * (1.f / DD);
        const float var  = c * (1.f / DD) - mean * mean;
        mb[0] = mean;
        mb[1] = rsqrtf(var + 1e-5f);
    }
    __syncthreads();
    const float mean = mb[0], rstd = mb[1];

    float4 gg = *(const float4*)&g[tid * 4];
    float4 bb = *(const float4*)&bta[tid * 4];
    float4 r;
    r.x = (v.x - mean) * rstd * gg.x + bb.x;
    r.y = (v.y - mean) * rstd * gg.y + bb.y;
    r.z = (v.z - mean) * rstd * gg.z + bb.z;
    r.w = (v.w - mean) * rstd * gg.w + bb.w;
    *(float4*)&out[off] = r;
}

// ---------------------------------------------------------------------------
extern "C" void kernel_launch(void* const* d_in, const int* in_sizes, int n_in,
                              void* d_out, int out_size)
{
    const float* X     = (const float*)d_in[0];
    const float* wq    = (const float*)d_in[1];
    const float* wk    = (const float*)d_in[2];
    const float* wv    = (const float*)d_in[3];
    const float* ln1_g = (const float*)d_in[4];
    const float* ln1_b = (const float*)d_in[5];
    const float* w1    = (const float*)d_in[6];
    const float* b1    = (const float*)d_in[7];
    const float* w2    = (const float*)d_in[8];
    const float* b2    = (const float*)d_in[9];
    const float* ln2_g = (const float*)d_in[10];
    const float* ln2_b = (const float*)d_in[11];
    float* out = (float*)d_out;

    float *pQ, *pK, *pV, *pCtx, *pX1, *pHb, *pY, *pY2;
    cudaGetSymbolAddress((void**)&pQ,   g_Q);
    cudaGetSymbolAddress((void**)&pK,   g_K);
    cudaGetSymbolAddress((void**)&pV,   g_V);
    cudaGetSymbolAddress((void**)&pCtx, g_ctx);
    cudaGetSymbolAddress((void**)&pX1,  g_X1);
    cudaGetSymbolAddress((void**)&pHb,  g_Hb);
    cudaGetSymbolAddress((void**)&pY,   g_Y);
    cudaGetSymbolAddress((void**)&pY2,  g_Y2);

    cudaFuncSetAttribute(gemm_mma<1>, cudaFuncAttributeMaxDynamicSharedMemorySize, GEMM_SMEM);
    cudaFuncSetAttribute(gemm_mma<3>, cudaFuncAttributeMaxDynamicSharedMemorySize, GEMM_SMEM);
    cudaFuncSetAttribute(gemm_mma<4>, cudaFuncAttributeMaxDynamicSharedMemorySize, GEMM_SMEM);
    cudaFuncSetAttribute(attn_tc,     cudaFuncAttributeMaxDynamicSharedMemorySize, ATT_SMEM);

    const dim3 blk(128);
    // Fused QKV projection (blockIdx.z selects weight/output)
    gemm_mma<3><<<dim3(DD/128, MM/128, 3), blk, GEMM_SMEM>>>(
        X, wq, wk, wv, pQ, pK, pV, nullptr, MM, DD, DD);
    attn_tc<<<dim3(LL/64, BB*HH), 128, ATT_SMEM>>>(pQ, pK, pV, pCtx);
    ln_kernel<<<MM, 256>>>(X, pCtx, nullptr, nullptr, ln1_g, ln1_b, pX1);
    // FFN up + SELU
    gemm_mma<1><<<dim3(DFF/128, MM/128), blk, GEMM_SMEM>>>(
        pX1, w1, nullptr, nullptr, pHb, nullptr, nullptr, b1, MM, DFF, DD);
    // FFN down, split-K=2
    gemm_mma<4><<<dim3(DD/128, MM/128, 2), blk, GEMM_SMEM>>>(
        pHb, w2, nullptr, nullptr, pY, pY2, nullptr, nullptr, MM, DD, DFF);
    // LN2( Y + Y2 + X1 + b2 ) -> out
    ln_kernel<<<MM, 256>>>(pY, pY2, pX1, b2, ln2_g, ln2_b, out);
}